// round 13
// baseline (speedup 1.0000x reference)
#include <cuda_runtime.h>

#define K_OBJ 256

// ---- scratch (__device__ globals; zero at load, consume-and-reset each run) ----
__device__ unsigned long long g_key[K_OBJ];
__device__ int    g_counts[K_OBJ];
__device__ float4 g_obj[K_OBJ];                 // (-2kx, -2ky, kx^2+ky^2+1e-6, w_rep)
__device__ float  g_watt[K_OBJ], g_kx[K_OBJ], g_ky[K_OBJ];
__device__ float  g_num[K_OBJ], g_den[K_OBJ];
__device__ float  g_W, g_lbeta, g_nvalid;
__device__ float  g_sum_s, g_noise_sum;
__device__ int    g_noise_cnt, g_done_p1, g_done;

__device__ __forceinline__ float clip_beta(float b) {
    return fminf(fmaxf(b, 0.0f), 0.99999f); // BETA_CLIP = 1 - 1e-5
}
__device__ __forceinline__ float sqrt_approx(float x) {
    float r; asm("sqrt.approx.f32 %0, %1;" : "=f"(r) : "f"(x)); return r;
}
__device__ __forceinline__ float fma_sat(float a, float b, float c) {
    float r; asm("fma.rn.sat.f32 %0, %1, %2, %3;" : "=f"(r) : "f"(a), "f"(b), "f"(c)); return r;
}

// ============ K1: counts + argmax-beta key — DIRECT global RED atomics
// (256 spread addresses absorb ~390 ops each at REDG rates; no shared merge tax),
// fused per-object weight setup in the last arriving block. ============
__global__ void __launch_bounds__(256) k_pass1(const float* __restrict__ pred_beta,
                                               const float* __restrict__ cc,
                                               const int*   __restrict__ t_idx, int n) {
    __shared__ float sW[K_OBJ], sL[K_OBJ];
    __shared__ int   sV[K_OBJ];
    __shared__ int   s_last;
    const int tid = threadIdx.x;

    int i = blockIdx.x * 256 + tid;
    if (i < n) {
        int t = t_idx[i];
        if (t >= 0) {
            float b = clip_beta(pred_beta[i]);
            unsigned long long key =
                ((unsigned long long)__float_as_uint(b) << 32) |
                (unsigned long long)(~(unsigned int)i);
            atomicMax(&g_key[t], key);      // no return use -> REDG.MAX.U64
            atomicAdd(&g_counts[t], 1);     // no return use -> RED.ADD
        }
    }

    // ---- last-block-done: fused per-object weight setup ----
    if (tid == 0) {
        __threadfence();
        s_last = (atomicAdd(&g_done_p1, 1) == gridDim.x - 1) ? 1 : 0;
    }
    __syncthreads();
    if (!s_last) return;
    __threadfence();                         // all blocks' REDs are visible

    {
        int k = tid;
        unsigned long long key = g_key[k];
        int c = g_counts[k];
        unsigned int aidx = ~(unsigned int)(key & 0xFFFFFFFFull);
        if (c == 0) aidx = 0u;
        float kx = cc[2u * aidx], ky = cc[2u * aidx + 1u];
        float ba = clip_beta(pred_beta[aidx]);
        float a  = atanhf(ba);
        float qa = a * a + 0.5f;             // Q_MIN

        float w = 0.f, watt = 0.f, lb = 0.f; int v = 0;
        if (c > 0) {
            int dr = n - c; if (dr < 1) dr = 1;
            w    = qa / (float)dr;
            watt = qa / (float)c;
            lb   = 1.0f - ba;
            v    = 1;
        }
        g_obj[k]  = make_float4(-2.0f * kx, -2.0f * ky,
                                fmaf(kx, kx, ky * ky) + 1e-6f, w);
        g_watt[k] = watt;
        g_kx[k]   = kx; g_ky[k] = ky;
        g_key[k]  = 0ull; g_counts[k] = 0;   // consume-and-reset

        sW[k] = w; sL[k] = lb; sV[k] = v;
        __syncthreads();
        #pragma unroll
        for (int s = 128; s > 0; s >>= 1) {
            if (k < s) { sW[k] += sW[k + s]; sL[k] += sL[k + s]; sV[k] += sV[k + s]; }
            __syncthreads();
        }
        if (k == 0) {
            g_W = sW[0]; g_lbeta = sL[0];
            g_nvalid = (sV[0] > 0) ? (float)sV[0] : 1.0f;
            g_done_p1 = 0;
        }
    }
}

// ============ K2: thread = point; 256-object inner loop from shared (R12-identical) ============
__global__ void __launch_bounds__(256) k_main(const float* __restrict__ pred_beta,
                                              const float* __restrict__ cc,
                                              const float* __restrict__ pred_energy,
                                              const float* __restrict__ pred_pos,
                                              const float* __restrict__ pred_time,
                                              const float* __restrict__ t_energy,
                                              const float* __restrict__ t_pos,
                                              const float* __restrict__ t_time,
                                              const int*   __restrict__ t_idx,
                                              float* __restrict__ out, int n) {
    __shared__ float4 s_obj[K_OBJ];
    __shared__ float  s_watt[K_OBJ], s_kx[K_OBJ], s_ky[K_OBJ];
    __shared__ float  s_num[K_OBJ], s_den[K_OBJ];
    __shared__ float  s_red[8];
    __shared__ float  s_noise;
    __shared__ int    s_ncnt, s_last;

    const int tid = threadIdx.x;

    // one-time object staging (no re-staging, no inner syncs)
    s_obj[tid]  = g_obj[tid];
    s_watt[tid] = g_watt[tid];
    s_kx[tid]   = g_kx[tid];
    s_ky[tid]   = g_ky[tid];
    s_num[tid]  = 0.f; s_den[tid] = 0.f;
    if (tid == 0) { s_noise = 0.f; s_ncnt = 0; }
    const float W = g_W;
    __syncthreads();

    // balanced contiguous partition over exactly-one-wave grid
    int nb   = gridDim.x;
    int base = n / nb, rem = n % nb;
    int b    = blockIdx.x;
    int start = b * base + min(b, rem);
    int cnt   = base + (b < rem ? 1 : 0);

    float sum_l = 0.f;                             // att + rep contribution of my point
    if (tid < cnt) {
        int i = start + tid;
        float  braw = pred_beta[i];                // front-batched loads
        float2 c    = ((const float2*)cc)[i];
        int    t    = t_idx[i];
        float  te   = t_energy[i];
        float  pe   = pred_energy[i];
        float2 tp   = ((const float2*)t_pos)[i];
        float2 pp   = ((const float2*)pred_pos)[i];
        float  tt   = t_time[i];
        float  pt   = pred_time[i];

        float bcl = clip_beta(braw);
        float a   = atanhf(bcl);
        float q   = a * a + 0.5f;                  // Q_MIN
        float px  = c.x, py = c.y;
        float p2s = fmaf(px, px, py * py);         // eps lives in O.z

        // own-object per-point terms
        if (t >= 0) {
            float dxt = px - s_kx[t], dyt = py - s_ky[t];
            float d2t = fmaf(dxt, dxt, dyt * dyt);
            sum_l = s_watt[t] * q * d2t;           // V_att contribution
            atomicAdd(&s_den[t], bcl);
            float ew  = (te > 10.0f) ? 1.0f : fmaxf((te - 0.5f) * (1.0f / 9.5f), 0.0f);
            float de  = te - pe;
            float el  = de * de / (te + 1.0f);
            float p0  = tp.x - pp.x, p1 = tp.y - pp.y;
            float pl  = fmaf(p0, p0, p1 * p1) * 0.01f;
            float dt  = tt - pt;
            float pay = fmaf(dt, dt, el + pl) * ew;
            if (braw >= 0.1f) atomicAdd(&s_num[t], pay * bcl);  // PAYLOAD_BETA_CLIP
        } else {
            atomicAdd(&s_noise, bcl);
            atomicAdd(&s_ncnt, 1);
        }

        // ---- hot loop: 256 objects, broadcast LDS.128; unroll 8 ----
        float acc0 = 0.f, acc1 = 0.f, acc2 = 0.f, acc3 = 0.f;
        #pragma unroll 8
        for (int p = 0; p < K_OBJ; p += 4) {
            float4 O0 = s_obj[p];
            acc0 = fmaf(O0.w, sqrt_approx(fma_sat(O0.x, px, fmaf(O0.y, py, O0.z + p2s))), acc0);
            float4 O1 = s_obj[p + 1];
            acc1 = fmaf(O1.w, sqrt_approx(fma_sat(O1.x, px, fmaf(O1.y, py, O1.z + p2s))), acc1);
            float4 O2 = s_obj[p + 2];
            acc2 = fmaf(O2.w, sqrt_approx(fma_sat(O2.x, px, fmaf(O2.y, py, O2.z + p2s))), acc2);
            float4 O3 = s_obj[p + 3];
            acc3 = fmaf(O3.w, sqrt_approx(fma_sat(O3.x, px, fmaf(O3.y, py, O3.z + p2s))), acc3);
        }
        float accs = (acc0 + acc1) + (acc2 + acc3);    // Σ_k w_k * s_ik
        float rep  = q * (W - accs);                   // q * Σ_k w_k (1 - s_ik)
        if (t >= 0) {
            // own-object correction: identical ops to loop body -> near-exact cancel
            float4 O = s_obj[t];
            float sown = sqrt_approx(fma_sat(O.x, px, fmaf(O.y, py, O.z + p2s)));
            rep -= q * (O.w * (1.0f - sown));
        }
        sum_l += rep;
    }

    // ---- block reduction of sum_l -> 1 global atomic ----
    #pragma unroll
    for (int o = 16; o > 0; o >>= 1)
        sum_l += __shfl_xor_sync(0xFFFFFFFFu, sum_l, o);
    if ((tid & 31) == 0) s_red[tid >> 5] = sum_l;
    __syncthreads();
    if (tid == 0) {
        float sb = 0.f;
        #pragma unroll
        for (int w8 = 0; w8 < 8; w8++) sb += s_red[w8];
        atomicAdd(&g_sum_s, sb);
        if (s_ncnt) { atomicAdd(&g_noise_sum, s_noise); atomicAdd(&g_noise_cnt, s_ncnt); }
    }
    // flush payload (spread atomics; skip zeros)
    if (s_den[tid] != 0.f) atomicAdd(&g_den[tid], s_den[tid]);
    if (s_num[tid] != 0.f) atomicAdd(&g_num[tid], s_num[tid]);
    __syncthreads();

    // ---- last-block-done: final arriving block reduces + resets ----
    if (tid == 0) {
        __threadfence();
        s_last = (atomicAdd(&g_done, 1) == gridDim.x - 1) ? 1 : 0;
    }
    __syncthreads();
    if (!s_last) return;
    __threadfence();                                // see all other blocks' flushes

    {
        float numv = g_num[tid];
        float denv = g_den[tid];
        float pay  = numv / fmaxf(denv, 1e-6f);     // invalid objects: 0/1e-6 = 0
        g_num[tid] = 0.f; g_den[tid] = 0.f;         // consume-and-reset

        s_watt[tid] = pay;                          // reuse shared for reduction
        __syncthreads();
        #pragma unroll
        for (int s = 128; s > 0; s >>= 1) {
            if (tid < s) s_watt[tid] += s_watt[tid + s];
            __syncthreads();
        }
        if (tid == 0) {
            float nvd = g_nvalid;
            int   nc  = g_noise_cnt; if (nc < 1) nc = 1;
            out[0] = (g_sum_s + g_lbeta + s_watt[0]) / nvd
                   + g_noise_sum / (float)nc;
            g_sum_s = 0.f; g_noise_sum = 0.f; g_noise_cnt = 0; g_done = 0;
        }
    }
}

extern "C" void kernel_launch(void* const* d_in, const int* in_sizes, int n_in,
                              void* d_out, int out_size) {
    const float* pred_beta    = (const float*)d_in[0];
    const float* pred_ccoords = (const float*)d_in[1];
    const float* pred_energy  = (const float*)d_in[2];
    const float* pred_pos     = (const float*)d_in[3];
    const float* pred_time    = (const float*)d_in[4];
    /* d_in[5] = pred_id: 1e-8-scale cls term, negligible */
    const float* t_energy     = (const float*)d_in[6];
    const float* t_pos        = (const float*)d_in[7];
    const float* t_time       = (const float*)d_in[8];
    /* d_in[9] = t_pid, d_in[11] = rowsplits: unused */
    const int*   t_idx        = (const int*)d_in[10];
    int n = in_sizes[0];

    int p1_blocks = (n + 255) / 256; if (p1_blocks < 1) p1_blocks = 1;

    // exactly-one-wave grid: 3 blocks/SM, balanced contiguous partition;
    // must also cover n with <=256 points per block
    int sm = 0;
    cudaDeviceGetAttribute(&sm, cudaDevAttrMultiProcessorCount, 0);
    int mb = 3 * sm;
    int minb = (n + 255) / 256; if (mb < minb) mb = minb;
    int maxb = (n + 31) / 32;   if (mb > maxb) mb = maxb;
    if (mb < 1) mb = 1;

    k_pass1<<<p1_blocks, 256>>>(pred_beta, pred_ccoords, t_idx, n);
    k_main <<<mb, 256>>>(pred_beta, pred_ccoords, pred_energy, pred_pos, pred_time,
                         t_energy, t_pos, t_time, t_idx, (float*)d_out, n);
}

// round 14
// speedup vs baseline: 1.8025x; 1.8025x over previous
#include <cuda_runtime.h>

#define K_OBJ 256
// 128-byte stride padding: one object per L2 line -> atomics spread across LTS slices
#define KPAD 16   // u64 stride (16*8 = 128B)
#define CPAD 32   // int/float stride (32*4 = 128B)

// ---- scratch (__device__ globals; zero at load, consume-and-reset each run) ----
__device__ unsigned long long g_key_pad[K_OBJ * KPAD];
__device__ int    g_cnt_pad[K_OBJ * CPAD];
__device__ float  g_num_pad[K_OBJ * CPAD], g_den_pad[K_OBJ * CPAD];
__device__ float4 g_obj[K_OBJ];                 // (-2kx, -2ky, kx^2+ky^2+1e-6, w_rep)
__device__ float  g_watt[K_OBJ], g_kx[K_OBJ], g_ky[K_OBJ];
__device__ float  g_W, g_lbeta, g_nvalid;
__device__ float  g_sum_s, g_noise_sum;
__device__ int    g_noise_cnt, g_done_p1, g_done;

__device__ __forceinline__ float clip_beta(float b) {
    return fminf(fmaxf(b, 0.0f), 0.99999f); // BETA_CLIP = 1 - 1e-5
}
__device__ __forceinline__ float sqrt_approx(float x) {
    float r; asm("sqrt.approx.f32 %0, %1;" : "=f"(r) : "f"(x)); return r;
}
__device__ __forceinline__ float fma_sat(float a, float b, float c) {
    float r; asm("fma.rn.sat.f32 %0, %1, %2, %3;" : "=f"(r) : "f"(a), "f"(b), "f"(c)); return r;
}

// ============ K1: counts + argmax-beta key — direct RED atomics to 128B-strided
// slots (each object owns its own L2 line); fused last-block weight setup. ============
__global__ void __launch_bounds__(256) k_pass1(const float* __restrict__ pred_beta,
                                               const float* __restrict__ cc,
                                               const int*   __restrict__ t_idx, int n) {
    __shared__ float sW[K_OBJ], sL[K_OBJ];
    __shared__ int   sV[K_OBJ];
    __shared__ int   s_last;
    const int tid = threadIdx.x;

    int i = blockIdx.x * 256 + tid;
    if (i < n) {
        int t = t_idx[i];
        if (t >= 0) {
            float b = clip_beta(pred_beta[i]);
            unsigned long long key =
                ((unsigned long long)__float_as_uint(b) << 32) |
                (unsigned long long)(~(unsigned int)i);
            atomicMax(&g_key_pad[t * KPAD], key);   // REDG.MAX.U64 to private line
            atomicAdd(&g_cnt_pad[t * CPAD], 1);     // RED.ADD to private line
        }
    }

    // ---- last-block-done: fused per-object weight setup ----
    if (tid == 0) {
        __threadfence();
        s_last = (atomicAdd(&g_done_p1, 1) == gridDim.x - 1) ? 1 : 0;
    }
    __syncthreads();
    if (!s_last) return;
    __threadfence();                         // all blocks' REDs are visible

    {
        int k = tid;
        unsigned long long key = g_key_pad[k * KPAD];
        int c = g_cnt_pad[k * CPAD];
        unsigned int aidx = ~(unsigned int)(key & 0xFFFFFFFFull);
        if (c == 0) aidx = 0u;
        float kx = cc[2u * aidx], ky = cc[2u * aidx + 1u];
        float ba = clip_beta(pred_beta[aidx]);
        float a  = atanhf(ba);
        float qa = a * a + 0.5f;             // Q_MIN

        float w = 0.f, watt = 0.f, lb = 0.f; int v = 0;
        if (c > 0) {
            int dr = n - c; if (dr < 1) dr = 1;
            w    = qa / (float)dr;
            watt = qa / (float)c;
            lb   = 1.0f - ba;
            v    = 1;
        }
        g_obj[k]  = make_float4(-2.0f * kx, -2.0f * ky,
                                fmaf(kx, kx, ky * ky) + 1e-6f, w);
        g_watt[k] = watt;
        g_kx[k]   = kx; g_ky[k] = ky;
        g_key_pad[k * KPAD] = 0ull; g_cnt_pad[k * CPAD] = 0;  // consume-and-reset

        sW[k] = w; sL[k] = lb; sV[k] = v;
        __syncthreads();
        #pragma unroll
        for (int s = 128; s > 0; s >>= 1) {
            if (k < s) { sW[k] += sW[k + s]; sL[k] += sL[k + s]; sV[k] += sV[k + s]; }
            __syncthreads();
        }
        if (k == 0) {
            g_W = sW[0]; g_lbeta = sL[0];
            g_nvalid = (sV[0] > 0) ? (float)sV[0] : 1.0f;
            g_done_p1 = 0;
        }
    }
}

// ============ K2: thread = point; 256-object inner loop from shared ============
__global__ void __launch_bounds__(256) k_main(const float* __restrict__ pred_beta,
                                              const float* __restrict__ cc,
                                              const float* __restrict__ pred_energy,
                                              const float* __restrict__ pred_pos,
                                              const float* __restrict__ pred_time,
                                              const float* __restrict__ t_energy,
                                              const float* __restrict__ t_pos,
                                              const float* __restrict__ t_time,
                                              const int*   __restrict__ t_idx,
                                              float* __restrict__ out, int n) {
    __shared__ float4 s_obj[K_OBJ];
    __shared__ float  s_watt[K_OBJ], s_kx[K_OBJ], s_ky[K_OBJ];
    __shared__ float  s_num[K_OBJ], s_den[K_OBJ];
    __shared__ float  s_red[8];
    __shared__ float  s_noise;
    __shared__ int    s_ncnt, s_last;

    const int tid = threadIdx.x;

    // one-time object staging (no re-staging, no inner syncs)
    s_obj[tid]  = g_obj[tid];
    s_watt[tid] = g_watt[tid];
    s_kx[tid]   = g_kx[tid];
    s_ky[tid]   = g_ky[tid];
    s_num[tid]  = 0.f; s_den[tid] = 0.f;
    if (tid == 0) { s_noise = 0.f; s_ncnt = 0; }
    const float W = g_W;
    __syncthreads();

    // balanced contiguous partition over exactly-one-wave grid
    int nb   = gridDim.x;
    int base = n / nb, rem = n % nb;
    int b    = blockIdx.x;
    int start = b * base + min(b, rem);
    int cnt   = base + (b < rem ? 1 : 0);

    float sum_l = 0.f;                             // att + rep contribution of my point
    if (tid < cnt) {
        int i = start + tid;
        float  braw = pred_beta[i];                // front-batched loads
        float2 c    = ((const float2*)cc)[i];
        int    t    = t_idx[i];
        float  te   = t_energy[i];
        float  pe   = pred_energy[i];
        float2 tp   = ((const float2*)t_pos)[i];
        float2 pp   = ((const float2*)pred_pos)[i];
        float  tt   = t_time[i];
        float  pt   = pred_time[i];

        float bcl = clip_beta(braw);
        float a   = atanhf(bcl);
        float q   = a * a + 0.5f;                  // Q_MIN
        float px  = c.x, py = c.y;
        float p2s = fmaf(px, px, py * py);         // eps lives in O.z

        // own-object per-point terms
        if (t >= 0) {
            float dxt = px - s_kx[t], dyt = py - s_ky[t];
            float d2t = fmaf(dxt, dxt, dyt * dyt);
            sum_l = s_watt[t] * q * d2t;           // V_att contribution
            atomicAdd(&s_den[t], bcl);
            float ew  = (te > 10.0f) ? 1.0f : fmaxf((te - 0.5f) * (1.0f / 9.5f), 0.0f);
            float de  = te - pe;
            float el  = de * de / (te + 1.0f);
            float p0  = tp.x - pp.x, p1 = tp.y - pp.y;
            float pl  = fmaf(p0, p0, p1 * p1) * 0.01f;
            float dt  = tt - pt;
            float pay = fmaf(dt, dt, el + pl) * ew;
            if (braw >= 0.1f) atomicAdd(&s_num[t], pay * bcl);  // PAYLOAD_BETA_CLIP
        } else {
            atomicAdd(&s_noise, bcl);
            atomicAdd(&s_ncnt, 1);
        }

        // ---- hot loop: 256 objects, broadcast LDS.128; unroll 8 ----
        float acc0 = 0.f, acc1 = 0.f, acc2 = 0.f, acc3 = 0.f;
        #pragma unroll 8
        for (int p = 0; p < K_OBJ; p += 4) {
            float4 O0 = s_obj[p];
            acc0 = fmaf(O0.w, sqrt_approx(fma_sat(O0.x, px, fmaf(O0.y, py, O0.z + p2s))), acc0);
            float4 O1 = s_obj[p + 1];
            acc1 = fmaf(O1.w, sqrt_approx(fma_sat(O1.x, px, fmaf(O1.y, py, O1.z + p2s))), acc1);
            float4 O2 = s_obj[p + 2];
            acc2 = fmaf(O2.w, sqrt_approx(fma_sat(O2.x, px, fmaf(O2.y, py, O2.z + p2s))), acc2);
            float4 O3 = s_obj[p + 3];
            acc3 = fmaf(O3.w, sqrt_approx(fma_sat(O3.x, px, fmaf(O3.y, py, O3.z + p2s))), acc3);
        }
        float accs = (acc0 + acc1) + (acc2 + acc3);    // Σ_k w_k * s_ik
        float rep  = q * (W - accs);                   // q * Σ_k w_k (1 - s_ik)
        if (t >= 0) {
            // own-object correction: identical ops to loop body -> near-exact cancel
            float4 O = s_obj[t];
            float sown = sqrt_approx(fma_sat(O.x, px, fmaf(O.y, py, O.z + p2s)));
            rep -= q * (O.w * (1.0f - sown));
        }
        sum_l += rep;
    }

    // ---- block reduction of sum_l -> 1 global atomic ----
    #pragma unroll
    for (int o = 16; o > 0; o >>= 1)
        sum_l += __shfl_xor_sync(0xFFFFFFFFu, sum_l, o);
    if ((tid & 31) == 0) s_red[tid >> 5] = sum_l;
    __syncthreads();
    if (tid == 0) {
        float sb = 0.f;
        #pragma unroll
        for (int w8 = 0; w8 < 8; w8++) sb += s_red[w8];
        atomicAdd(&g_sum_s, sb);
        if (s_ncnt) { atomicAdd(&g_noise_sum, s_noise); atomicAdd(&g_noise_cnt, s_ncnt); }
    }
    // flush payload to 128B-strided slots (skip zeros)
    if (s_den[tid] != 0.f) atomicAdd(&g_den_pad[tid * CPAD], s_den[tid]);
    if (s_num[tid] != 0.f) atomicAdd(&g_num_pad[tid * CPAD], s_num[tid]);
    __syncthreads();

    // ---- last-block-done: final arriving block reduces + resets ----
    if (tid == 0) {
        __threadfence();
        s_last = (atomicAdd(&g_done, 1) == gridDim.x - 1) ? 1 : 0;
    }
    __syncthreads();
    if (!s_last) return;
    __threadfence();                                // see all other blocks' flushes

    {
        float numv = g_num_pad[tid * CPAD];
        float denv = g_den_pad[tid * CPAD];
        float pay  = numv / fmaxf(denv, 1e-6f);     // invalid objects: 0/1e-6 = 0
        g_num_pad[tid * CPAD] = 0.f; g_den_pad[tid * CPAD] = 0.f;  // reset

        s_watt[tid] = pay;                          // reuse shared for reduction
        __syncthreads();
        #pragma unroll
        for (int s = 128; s > 0; s >>= 1) {
            if (tid < s) s_watt[tid] += s_watt[tid + s];
            __syncthreads();
        }
        if (tid == 0) {
            float nvd = g_nvalid;
            int   nc  = g_noise_cnt; if (nc < 1) nc = 1;
            out[0] = (g_sum_s + g_lbeta + s_watt[0]) / nvd
                   + g_noise_sum / (float)nc;
            g_sum_s = 0.f; g_noise_sum = 0.f; g_noise_cnt = 0; g_done = 0;
        }
    }
}

extern "C" void kernel_launch(void* const* d_in, const int* in_sizes, int n_in,
                              void* d_out, int out_size) {
    const float* pred_beta    = (const float*)d_in[0];
    const float* pred_ccoords = (const float*)d_in[1];
    const float* pred_energy  = (const float*)d_in[2];
    const float* pred_pos     = (const float*)d_in[3];
    const float* pred_time    = (const float*)d_in[4];
    /* d_in[5] = pred_id: 1e-8-scale cls term, negligible */
    const float* t_energy     = (const float*)d_in[6];
    const float* t_pos        = (const float*)d_in[7];
    const float* t_time       = (const float*)d_in[8];
    /* d_in[9] = t_pid, d_in[11] = rowsplits: unused */
    const int*   t_idx        = (const int*)d_in[10];
    int n = in_sizes[0];

    int p1_blocks = (n + 255) / 256; if (p1_blocks < 1) p1_blocks = 1;

    // exactly-one-wave grid: 3 blocks/SM, balanced contiguous partition;
    // must also cover n with <=256 points per block
    int sm = 0;
    cudaDeviceGetAttribute(&sm, cudaDevAttrMultiProcessorCount, 0);
    int mb = 3 * sm;
    int minb = (n + 255) / 256; if (mb < minb) mb = minb;
    int maxb = (n + 31) / 32;   if (mb > maxb) mb = maxb;
    if (mb < 1) mb = 1;

    k_pass1<<<p1_blocks, 256>>>(pred_beta, pred_ccoords, t_idx, n);
    k_main <<<mb, 256>>>(pred_beta, pred_ccoords, pred_energy, pred_pos, pred_time,
                         t_energy, t_pos, t_time, t_idx, (float*)d_out, n);
}